// round 3
// baseline (speedup 1.0000x reference)
#include <cuda_runtime.h>
#include <cuda_fp16.h>
#include <cstdint>

// Problem constants
#define A_CAPS   32
#define B_CAPS   32
#define CDIM     16
#define KKA      288          // 9 * 32
#define JD       512          // B*D
#define OH       15
#define OW       15
#define LPOS     225          // OH*OW
#define BATCH    4
#define MTOT     900          // BATCH * LPOS
#define M_TILE   36           // 900 / 36 = 25 tiles
#define WS_STR   516          // padded row stride for Ws [c][jd]

// 265 MB votes scratch (fp16): [m][k][jd]
__device__ __align__(16) __half g_votes[(size_t)MTOT * KKA * JD];

// ---------------------------------------------------------------------------
// K1: votes[m][k][jd] = sum_c W[k][jd][c] * p[m][k][c]   (fp32 math, fp16 store)
// p[m][k][c] = pose[b, a*16+c, 2*oy+ki, 2*ox+kj], k = kk*32+a, kk = ki*3+kj
// grid (KKA, MTOT/M_TILE), 256 threads
// ---------------------------------------------------------------------------
__global__ void __launch_bounds__(256) votes_kernel(
    const float* __restrict__ pose, const float* __restrict__ W)
{
    __shared__ __align__(16) float Ws[CDIM * WS_STR];   // transposed: [c][jd]
    __shared__ float Ps[M_TILE][CDIM];

    const int k  = blockIdx.x;
    const int m0 = blockIdx.y * M_TILE;
    const int t  = threadIdx.x;

    // Load W[k] (512x16) transposed into smem
    const float* Wk = W + (size_t)k * (JD * CDIM);
    for (int i = t; i < JD * CDIM; i += 256) {
        int jd = i >> 4, c = i & 15;
        Ws[c * WS_STR + jd] = Wk[i];
    }

    // Load pose slices for the M_TILE sites
    const int a  = k & 31;
    const int kk = k >> 5;
    const int ki = kk / 3, kj = kk % 3;
    for (int i = t; i < M_TILE * CDIM; i += 256) {
        int mi = i >> 4, c = i & 15;
        int m  = m0 + mi;
        int b  = m / LPOS, l = m % LPOS;
        int oy = l / OW,   ox = l % OW;
        int y  = 2 * oy + ki, x = 2 * ox + kj;
        Ps[mi][c] = pose[(((size_t)b * (A_CAPS * CDIM) + a * CDIM + c) * 32 + y) * 32 + x];
    }
    __syncthreads();

    const int jdg   = t & 127;     // jd group of 4: jd = 4*jdg
    const int mslot = t >> 7;      // 0 or 1

    for (int mi = mslot; mi < M_TILE; mi += 2) {
        float p[CDIM];
        #pragma unroll
        for (int c = 0; c < CDIM; c++) p[c] = Ps[mi][c];

        float4 acc = make_float4(0.f, 0.f, 0.f, 0.f);
        #pragma unroll
        for (int c = 0; c < CDIM; c++) {
            float4 w4 = *reinterpret_cast<const float4*>(&Ws[c * WS_STR + 4 * jdg]);
            acc.x += w4.x * p[c];
            acc.y += w4.y * p[c];
            acc.z += w4.z * p[c];
            acc.w += w4.w * p[c];
        }
        __half2 h0 = __floats2half2_rn(acc.x, acc.y);
        __half2 h1 = __floats2half2_rn(acc.z, acc.w);
        uint2 st;
        st.x = *reinterpret_cast<uint32_t*>(&h0);
        st.y = *reinterpret_cast<uint32_t*>(&h1);
        *reinterpret_cast<uint2*>(
            &g_votes[((size_t)(m0 + mi) * KKA + k) * JD + 4 * jdg]) = st;
    }
}

// ---------------------------------------------------------------------------
// K2: routing-by-agreement, one block per (b,l) site, 256 threads.
// Thread t owns jd pair (2t, 2t+1); both live in output capsule j = t>>3;
// lane8 = t&7 indexes the 8 threads (16 d-dims) of capsule j.
// ---------------------------------------------------------------------------

__device__ __forceinline__ void squash_to_v(
    float2 s, int t, int j, int lane8, float* n2_s, float* v_s)
{
    float q = s.x * s.x + s.y * s.y;
    #pragma unroll
    for (int off = 4; off > 0; off >>= 1)
        q += __shfl_down_sync(0xffffffffu, q, off, 8);
    if (lane8 == 0) n2_s[j] = q;
    __syncthreads();
    float n2 = n2_s[j];
    float f  = n2 / ((1.f + n2) * sqrtf(n2 + 1e-8f));
    v_s[2 * t]     = s.x * f;
    v_s[2 * t + 1] = s.y * f;
    __syncthreads();
}

template <bool FIRST>
__device__ __forceinline__ void route_pass(
    const __half* __restrict__ base,
    float* logits, float* c_s, float* n2_s, float* v_s,
    int t, int j, int lane8)
{
    const float2 vv = make_float2(v_s[2 * t], v_s[2 * t + 1]);
    float2 sa = make_float2(0.f, 0.f);
    const int w = t >> 5, lane = t & 31;

    for (int kc = 0; kc < KKA; kc += 8) {
        float2 vt[8];
        #pragma unroll
        for (int i = 0; i < 8; i++) {
            __half2 h = *reinterpret_cast<const __half2*>(
                base + (size_t)(kc + i) * JD + 2 * t);
            vt[i] = __half22float2(h);
        }
        // logits update: dot(v_j, votes_kj) over d (8-lane groups, 2 d per lane)
        #pragma unroll
        for (int i = 0; i < 8; i++) {
            float d = vt[i].x * vv.x + vt[i].y * vv.y;
            #pragma unroll
            for (int off = 4; off > 0; off >>= 1)
                d += __shfl_down_sync(0xffffffffu, d, off, 8);
            if (lane8 == 0) {
                int idx = (kc + i) * 32 + j;
                if (FIRST) logits[idx] = d;
                else       logits[idx] += d;
            }
        }
        __syncthreads();
        // softmax over B=32 for the 8 rows, one warp per row
        {
            float lg = logits[(kc + w) * 32 + lane];
            float mx = lg;
            #pragma unroll
            for (int off = 16; off > 0; off >>= 1)
                mx = fmaxf(mx, __shfl_xor_sync(0xffffffffu, mx, off));
            float e = __expf(lg - mx);
            float sm = e;
            #pragma unroll
            for (int off = 16; off > 0; off >>= 1)
                sm += __shfl_xor_sync(0xffffffffu, sm, off);
            c_s[w * 32 + lane] = e / sm;
        }
        __syncthreads();
        // s accumulation
        #pragma unroll
        for (int i = 0; i < 8; i++) {
            float c = c_s[i * 32 + j];
            sa.x += c * vt[i].x;
            sa.y += c * vt[i].y;
        }
    }
    squash_to_v(sa, t, j, lane8, n2_s, v_s);
}

__global__ void __launch_bounds__(256) routing_kernel(float* __restrict__ out)
{
    __shared__ float logits[KKA * 32];   // 36 KB
    __shared__ float v_s[JD];
    __shared__ float c_s[8 * 32];
    __shared__ float n2_s[32];

    const int m = blockIdx.x;
    const __half* base = g_votes + (size_t)m * (KKA * JD);
    const int t = threadIdx.x;
    const int j = t >> 3;
    const int lane8 = t & 7;

    // ---- iteration 1: c = 1/32 uniform -> s = mean over k ----
    float2 s = make_float2(0.f, 0.f);
    #pragma unroll 8
    for (int k = 0; k < KKA; k++) {
        __half2 h = *reinterpret_cast<const __half2*>(base + (size_t)k * JD + 2 * t);
        float2 f = __half22float2(h);
        s.x += f.x; s.y += f.y;
    }
    s.x *= (1.f / 32.f);
    s.y *= (1.f / 32.f);
    squash_to_v(s, t, j, lane8, n2_s, v_s);     // v1

    // ---- iteration 2: logits = v1.votes ; softmax ; s2 ----
    route_pass<true>(base, logits, c_s, n2_s, v_s, t, j, lane8);   // v2
    // ---- iteration 3: logits += v2.votes ; softmax ; s3 ----
    route_pass<false>(base, logits, c_s, n2_s, v_s, t, j, lane8);  // v3

    // output: out[b, jd, l]
    const int b = m / LPOS, l = m % LPOS;
    out[((size_t)b * JD + 2 * t) * LPOS + l]     = v_s[2 * t];
    out[((size_t)b * JD + 2 * t + 1) * LPOS + l] = v_s[2 * t + 1];
}

// ---------------------------------------------------------------------------
extern "C" void kernel_launch(void* const* d_in, const int* in_sizes, int n_in,
                              void* d_out, int out_size)
{
    const float* pose = (const float*)d_in[0];   // (4, 512, 32, 32)
    const float* W    = (const float*)d_in[1];   // (288, 512, 16)
    float* out        = (float*)d_out;           // (4, 512, 15, 15)

    dim3 g1(KKA, MTOT / M_TILE);
    votes_kernel<<<g1, 256>>>(pose, W);
    routing_kernel<<<MTOT, 256>>>(out);
}

// round 6
// speedup vs baseline: 1.0617x; 1.0617x over previous
#include <cuda_runtime.h>
#include <cuda_fp16.h>
#include <cstdint>

// Problem constants
#define A_CAPS   32
#define CDIM     16
#define KKA      288          // 9 * 32
#define JD       512          // B*D
#define OH       15
#define OW       15
#define LPOS     225          // OH*OW
#define BATCH    4
#define MTOT     900          // BATCH * LPOS
#define M_TILE   60           // 900 / 60 = 15 tiles
#define WS_STR   516          // padded row stride for Ws [c][jd]

// K2 dynamic smem: logits + v_s + c_s + n2_s + pad (occupancy cap -> 3 CTA/SM)
#define K2_PAD       7000
#define K2_SMEM_FLTS (KKA * 32 + JD + 256 + 32 + K2_PAD)
#define K2_SMEM_BYTES (K2_SMEM_FLTS * 4)

// 265 MB votes scratch (fp16): [m][k][jd]
__device__ __align__(16) __half g_votes[(size_t)MTOT * KKA * JD];

// ---- packed f32x2 helpers (sm_103a FFMA2) ----
__device__ __forceinline__ unsigned long long pk2(float x, float y) {
    unsigned long long r;
    asm("mov.b64 %0, {%1, %2};" : "=l"(r) : "f"(x), "f"(y));
    return r;
}
__device__ __forceinline__ unsigned long long ffma2(
    unsigned long long a, unsigned long long b, unsigned long long c) {
    unsigned long long d;
    asm("fma.rn.f32x2 %0, %1, %2, %3;" : "=l"(d) : "l"(a), "l"(b), "l"(c));
    return d;
}
__device__ __forceinline__ void upk2(unsigned long long v, float& lo, float& hi) {
    asm("mov.b64 {%0, %1}, %2;" : "=f"(lo), "=f"(hi) : "l"(v));
}

// ---------------------------------------------------------------------------
// K1: votes[m][k][jd] = sum_c W[k][jd][c] * p[m][k][c]   (f32x2 math, fp16 out)
// W slice held in registers across the m loop; p broadcast from smem.
// grid (KKA, MTOT/M_TILE), 256 threads
// ---------------------------------------------------------------------------
__global__ void __launch_bounds__(256, 2) votes_kernel(
    const float* __restrict__ pose, const float* __restrict__ W)
{
    __shared__ __align__(16) float Ws[CDIM * WS_STR];   // transposed: [c][jd]
    __shared__ float Ps[M_TILE][CDIM];

    const int k  = blockIdx.x;
    const int m0 = blockIdx.y * M_TILE;
    const int t  = threadIdx.x;

    // Stage W[k] (512x16) transposed into smem
    const float* Wk = W + (size_t)k * (JD * CDIM);
    for (int i = t; i < JD * CDIM; i += 256) {
        int jd = i >> 4, c = i & 15;
        Ws[c * WS_STR + jd] = Wk[i];
    }

    // Stage pose slices for M_TILE sites
    const int a  = k & 31;
    const int kk = k >> 5;
    const int ki = kk / 3, kj = kk % 3;
    for (int i = t; i < M_TILE * CDIM; i += 256) {
        int mi = i >> 4, c = i & 15;
        int m  = m0 + mi;
        int b  = m / LPOS, l = m % LPOS;
        int oy = l / OW,   ox = l % OW;
        int y  = 2 * oy + ki, x = 2 * ox + kj;
        Ps[mi][c] = pose[(((size_t)b * (A_CAPS * CDIM) + a * CDIM + c) * 32 + y) * 32 + x];
    }
    __syncthreads();

    const int jdg   = t & 127;     // jd group of 4: jd = 4*jdg
    const int mslot = t >> 7;      // 0 or 1 (both mslots share identical W regs)

    // Hoist this thread's W slice into packed registers (one-time)
    unsigned long long w01[CDIM], w23[CDIM];
    #pragma unroll
    for (int c = 0; c < CDIM; c++) {
        float4 w4 = *reinterpret_cast<const float4*>(&Ws[c * WS_STR + 4 * jdg]);
        w01[c] = pk2(w4.x, w4.y);
        w23[c] = pk2(w4.z, w4.w);
    }

    #pragma unroll 2
    for (int q = 0; q < M_TILE / 2; q++) {
        const int mi = 2 * q + mslot;
        unsigned long long a01 = 0ull, a23 = 0ull;   // (0.f,0.f) packed
        #pragma unroll
        for (int c = 0; c < CDIM; c++) {
            float p = Ps[mi][c];                      // LDS broadcast
            unsigned long long pp = pk2(p, p);
            a01 = ffma2(w01[c], pp, a01);
            a23 = ffma2(w23[c], pp, a23);
        }
        float x0, x1, x2, x3;
        upk2(a01, x0, x1);
        upk2(a23, x2, x3);
        __half2 h0 = __floats2half2_rn(x0, x1);
        __half2 h1 = __floats2half2_rn(x2, x3);
        uint2 st;
        st.x = *reinterpret_cast<uint32_t*>(&h0);
        st.y = *reinterpret_cast<uint32_t*>(&h1);
        *reinterpret_cast<uint2*>(
            &g_votes[((size_t)(m0 + mi) * KKA + k) * JD + 4 * jdg]) = st;
    }
}

// ---------------------------------------------------------------------------
// K2: routing-by-agreement, one block per (b,l) site, 256 threads.
// Thread t owns jd pair (2t, 2t+1); both in output capsule j = t>>3.
// Dynamic smem padded to cap occupancy at 3 CTAs/SM (L2 residency of votes).
// ---------------------------------------------------------------------------

__device__ __forceinline__ void squash_to_v(
    float2 s, int t, int j, int lane8, float* n2_s, float* v_s)
{
    float q = s.x * s.x + s.y * s.y;
    #pragma unroll
    for (int off = 4; off > 0; off >>= 1)
        q += __shfl_down_sync(0xffffffffu, q, off, 8);
    if (lane8 == 0) n2_s[j] = q;
    __syncthreads();
    float n2 = n2_s[j];
    float f  = n2 / ((1.f + n2) * sqrtf(n2 + 1e-8f));
    v_s[2 * t]     = s.x * f;
    v_s[2 * t + 1] = s.y * f;
    __syncthreads();
}

template <bool FIRST>
__device__ __forceinline__ void route_pass(
    const __half* __restrict__ base,
    float* logits, float* c_s, float* n2_s, float* v_s,
    int t, int j, int lane8)
{
    const float2 vv = make_float2(v_s[2 * t], v_s[2 * t + 1]);
    float2 sa = make_float2(0.f, 0.f);
    const int w = t >> 5, lane = t & 31;

    // prefetch chunk 0
    uint32_t pre[8];
    #pragma unroll
    for (int i = 0; i < 8; i++)
        pre[i] = *reinterpret_cast<const uint32_t*>(base + (size_t)i * JD + 2 * t);

    for (int kc = 0; kc < KKA; kc += 8) {
        uint32_t cur[8];
        #pragma unroll
        for (int i = 0; i < 8; i++) cur[i] = pre[i];
        if (kc + 8 < KKA) {
            #pragma unroll
            for (int i = 0; i < 8; i++)
                pre[i] = *reinterpret_cast<const uint32_t*>(
                    base + (size_t)(kc + 8 + i) * JD + 2 * t);
        }
        float2 vt[8];
        #pragma unroll
        for (int i = 0; i < 8; i++)
            vt[i] = __half22float2(*reinterpret_cast<__half2*>(&cur[i]));

        // logits update: dot(v_j, votes_kj) over d (8-lane groups, 2 d per lane)
        #pragma unroll
        for (int i = 0; i < 8; i++) {
            float d = vt[i].x * vv.x + vt[i].y * vv.y;
            #pragma unroll
            for (int off = 4; off > 0; off >>= 1)
                d += __shfl_down_sync(0xffffffffu, d, off, 8);
            if (lane8 == 0) {
                int idx = (kc + i) * 32 + j;
                if (FIRST) logits[idx] = d;
                else       logits[idx] += d;
            }
        }
        __syncthreads();
        // softmax over B=32 for the 8 rows, one warp per row
        {
            float lg = logits[(kc + w) * 32 + lane];
            float mx = lg;
            #pragma unroll
            for (int off = 16; off > 0; off >>= 1)
                mx = fmaxf(mx, __shfl_xor_sync(0xffffffffu, mx, off));
            float e = __expf(lg - mx);
            float sm = e;
            #pragma unroll
            for (int off = 16; off > 0; off >>= 1)
                sm += __shfl_xor_sync(0xffffffffu, sm, off);
            c_s[w * 32 + lane] = e / sm;
        }
        __syncthreads();
        // s accumulation
        #pragma unroll
        for (int i = 0; i < 8; i++) {
            float c = c_s[i * 32 + j];
            sa.x += c * vt[i].x;
            sa.y += c * vt[i].y;
        }
    }
    squash_to_v(sa, t, j, lane8, n2_s, v_s);
}

__global__ void __launch_bounds__(256) routing_kernel(float* __restrict__ out)
{
    extern __shared__ float sdyn[];
    float* logits = sdyn;                       // KKA*32
    float* v_s    = sdyn + KKA * 32;            // 512
    float* c_s    = v_s + JD;                   // 256
    float* n2_s   = c_s + 256;                  // 32

    const int m = blockIdx.x;
    const __half* base = g_votes + (size_t)m * (KKA * JD);
    const int t = threadIdx.x;
    const int j = t >> 3;
    const int lane8 = t & 7;

    // ---- iteration 1: c = 1/32 uniform -> s = mean over k ----
    float2 s = make_float2(0.f, 0.f);
    #pragma unroll 8
    for (int k = 0; k < KKA; k++) {
        __half2 h = *reinterpret_cast<const __half2*>(base + (size_t)k * JD + 2 * t);
        float2 f = __half22float2(h);
        s.x += f.x; s.y += f.y;
    }
    s.x *= (1.f / 32.f);
    s.y *= (1.f / 32.f);
    squash_to_v(s, t, j, lane8, n2_s, v_s);     // v1

    // ---- iteration 2: logits = v1.votes ; softmax ; s2 ----
    route_pass<true>(base, logits, c_s, n2_s, v_s, t, j, lane8);   // v2
    // ---- iteration 3: logits += v2.votes ; softmax ; s3 ----
    route_pass<false>(base, logits, c_s, n2_s, v_s, t, j, lane8);  // v3

    // output: out[b, jd, l]
    const int b = m / LPOS, l = m % LPOS;
    out[((size_t)b * JD + 2 * t) * LPOS + l]     = v_s[2 * t];
    out[((size_t)b * JD + 2 * t + 1) * LPOS + l] = v_s[2 * t + 1];
}

// ---------------------------------------------------------------------------
extern "C" void kernel_launch(void* const* d_in, const int* in_sizes, int n_in,
                              void* d_out, int out_size)
{
    const float* pose = (const float*)d_in[0];   // (4, 512, 32, 32)
    const float* W    = (const float*)d_in[1];   // (288, 512, 16)
    float* out        = (float*)d_out;           // (4, 512, 15, 15)

    cudaFuncSetAttribute(routing_kernel,
                         cudaFuncAttributeMaxDynamicSharedMemorySize,
                         K2_SMEM_BYTES);

    dim3 g1(KKA, MTOT / M_TILE);
    votes_kernel<<<g1, 256>>>(pose, W);
    routing_kernel<<<MTOT, 256, K2_SMEM_BYTES>>>(out);
}